// round 1
// baseline (speedup 1.0000x reference)
#include <cuda_runtime.h>

// relu(x @ W^T + b)
// x: [B*N, 2] f32, W: [256, 2] f32 (row-major: W[d][i]), b: [256] f32
// out: [B*N, 256] f32
//
// Pure streaming-store kernel: ~524 MB written, ~4 MB read.
// 64 threads per row, each thread -> 4 output columns via one float4 store.

#define D_MODEL 256
#define TPR (D_MODEL / 4)      // 64 threads per row
#define BLOCK_THREADS 256
#define ROWS_PER_BLOCK (BLOCK_THREADS / TPR)  // 4

__global__ __launch_bounds__(BLOCK_THREADS)
void embeddings_kernel(const float* __restrict__ x,
                       const float* __restrict__ W,
                       const float* __restrict__ b,
                       float* __restrict__ out,
                       int n_rows) {
    __shared__ float sW0[D_MODEL];
    __shared__ float sW1[D_MODEL];
    __shared__ float sB[D_MODEL];

    int tid = threadIdx.x;
    if (tid < D_MODEL) {
        sW0[tid] = W[tid * 2 + 0];
        sW1[tid] = W[tid * 2 + 1];
        sB[tid]  = b[tid];
    }
    __syncthreads();

    long long row = (long long)blockIdx.x * ROWS_PER_BLOCK + (tid / TPR);
    int lane = tid % TPR;            // 0..63, selects 4-col chunk
    if (row >= n_rows) return;

    // Row input: one float2 (broadcast across the 64 threads of this row)
    float2 xx = __ldg(reinterpret_cast<const float2*>(x) + row);

    int col = lane * 4;
    float4 y;
    y.x = fmaxf(fmaf(xx.x, sW0[col + 0], fmaf(xx.y, sW1[col + 0], sB[col + 0])), 0.0f);
    y.y = fmaxf(fmaf(xx.x, sW0[col + 1], fmaf(xx.y, sW1[col + 1], sB[col + 1])), 0.0f);
    y.z = fmaxf(fmaf(xx.x, sW0[col + 2], fmaf(xx.y, sW1[col + 2], sB[col + 2])), 0.0f);
    y.w = fmaxf(fmaf(xx.x, sW0[col + 3], fmaf(xx.y, sW1[col + 3], sB[col + 3])), 0.0f);

    reinterpret_cast<float4*>(out)[row * TPR + lane] = y;
}

extern "C" void kernel_launch(void* const* d_in, const int* in_sizes, int n_in,
                              void* d_out, int out_size) {
    const float* x = (const float*)d_in[0];   // [B, N, 2]
    const float* W = (const float*)d_in[1];   // [256, 2]
    const float* b = (const float*)d_in[2];   // [256]
    float* out = (float*)d_out;               // [B, N, 256]

    int n_rows = in_sizes[0] / 2;             // B*N = 512000

    int grid = (n_rows + ROWS_PER_BLOCK - 1) / ROWS_PER_BLOCK;
    embeddings_kernel<<<grid, BLOCK_THREADS>>>(x, W, b, out, n_rows);
}

// round 3
// speedup vs baseline: 1.3913x; 1.3913x over previous
#include <cuda_runtime.h>

// relu(x @ W^T + b)
// x: [B*N, 2] f32, W: [256, 2] f32 row-major (W[d][i]), b: [256] f32
// out: [B*N, 256] f32.  n_rows = 512000.
//
// R2 (resubmit after infra failure): weights hoisted to registers
// (loop-invariant per thread), grid-stride over rows, pointer-increment
// addressing. Steady-state per-row cost per thread:
// 1 broadcast LDG.64 + 8 FFMA + 4 FMAX + 1 STG.128. No shared memory.

#define D_MODEL 256
#define TPR 64                         // threads per row (64 x float4 = 256 cols)
#define BLOCK_THREADS 256
#define ROWS_PER_BLOCK 4               // concurrent row subgroups per block
#define ITERS 32                       // row-groups per block -> 128 rows/block

__global__ __launch_bounds__(BLOCK_THREADS)
void embeddings_kernel(const float* __restrict__ x,
                       const float* __restrict__ W,
                       const float* __restrict__ b,
                       float* __restrict__ out,
                       int n_rows) {
    int tid  = threadIdx.x;
    int lane = tid & (TPR - 1);        // 0..63 -> column chunk
    int sub  = tid >> 6;               // 0..3  -> row subgroup
    int col  = lane * 4;

    // This thread's 4 weight pairs + biases, loaded ONCE (tiny, L2 resident).
    float w0_0 = __ldg(&W[(col + 0) * 2]);
    float w1_0 = __ldg(&W[(col + 0) * 2 + 1]);
    float w0_1 = __ldg(&W[(col + 1) * 2]);
    float w1_1 = __ldg(&W[(col + 1) * 2 + 1]);
    float w0_2 = __ldg(&W[(col + 2) * 2]);
    float w1_2 = __ldg(&W[(col + 2) * 2 + 1]);
    float w0_3 = __ldg(&W[(col + 3) * 2]);
    float w1_3 = __ldg(&W[(col + 3) * 2 + 1]);
    float b_0  = __ldg(&b[col + 0]);
    float b_1  = __ldg(&b[col + 1]);
    float b_2  = __ldg(&b[col + 2]);
    float b_3  = __ldg(&b[col + 3]);

    long long row0 = (long long)blockIdx.x * (ROWS_PER_BLOCK * ITERS) + sub;

    const float2* __restrict__ xp = reinterpret_cast<const float2*>(x) + row0;
    float4* __restrict__       op = reinterpret_cast<float4*>(out) + row0 * TPR + lane;

    long long rows_left = (long long)n_rows - row0;

    #pragma unroll 4
    for (int i = 0; i < ITERS; i++) {
        if ((long long)i * ROWS_PER_BLOCK >= rows_left) break;

        float2 xx = __ldg(xp);         // broadcast across the 64 lanes of this row

        float4 y;
        y.x = fmaxf(fmaf(xx.x, w0_0, fmaf(xx.y, w1_0, b_0)), 0.0f);
        y.y = fmaxf(fmaf(xx.x, w0_1, fmaf(xx.y, w1_1, b_1)), 0.0f);
        y.z = fmaxf(fmaf(xx.x, w0_2, fmaf(xx.y, w1_2, b_2)), 0.0f);
        y.w = fmaxf(fmaf(xx.x, w0_3, fmaf(xx.y, w1_3, b_3)), 0.0f);

        *op = y;

        xp += ROWS_PER_BLOCK;
        op += ROWS_PER_BLOCK * TPR;
    }
}

extern "C" void kernel_launch(void* const* d_in, const int* in_sizes, int n_in,
                              void* d_out, int out_size) {
    const float* x = (const float*)d_in[0];   // [B, N, 2]
    const float* W = (const float*)d_in[1];   // [256, 2]
    const float* b = (const float*)d_in[2];   // [256]
    float* out = (float*)d_out;               // [B, N, 256]

    int n_rows = in_sizes[0] / 2;             // B*N = 512000

    int rows_per_block = ROWS_PER_BLOCK * ITERS;   // 128
    int grid = (n_rows + rows_per_block - 1) / rows_per_block;   // 4000
    embeddings_kernel<<<grid, BLOCK_THREADS>>>(x, W, b, out, n_rows);
}

// round 4
// speedup vs baseline: 1.5550x; 1.1177x over previous
#include <cuda_runtime.h>

// relu(x @ W^T + b)
// x: [B*N, 2] f32, W: [256, 2] f32 row-major (W[d][i]), b: [256] f32
// out: [B*N, 256] f32.  n_rows = 512000.
//
// R4: R3 structure + streaming stores (__stcs, evict-first in L2 -- output is
// never re-read) + unroll 8 for deeper store MLP per warp.
// Steady-state per-row per-thread: 1 broadcast LDG.64 + 8 FFMA + 4 FMAX +
// 1 STG.128.CS. No shared memory.

#define D_MODEL 256
#define TPR 64                         // threads per row (64 x float4 = 256 cols)
#define BLOCK_THREADS 256
#define ROWS_PER_BLOCK 4               // concurrent row subgroups per block
#define ITERS 32                       // row-groups per block -> 128 rows/block

__global__ __launch_bounds__(BLOCK_THREADS)
void embeddings_kernel(const float* __restrict__ x,
                       const float* __restrict__ W,
                       const float* __restrict__ b,
                       float* __restrict__ out,
                       int n_rows) {
    int tid  = threadIdx.x;
    int lane = tid & (TPR - 1);        // 0..63 -> column chunk
    int sub  = tid >> 6;               // 0..3  -> row subgroup
    int col  = lane * 4;

    // This thread's 4 weight pairs + biases, loaded ONCE (tiny, L2 resident).
    float w0_0 = __ldg(&W[(col + 0) * 2]);
    float w1_0 = __ldg(&W[(col + 0) * 2 + 1]);
    float w0_1 = __ldg(&W[(col + 1) * 2]);
    float w1_1 = __ldg(&W[(col + 1) * 2 + 1]);
    float w0_2 = __ldg(&W[(col + 2) * 2]);
    float w1_2 = __ldg(&W[(col + 2) * 2 + 1]);
    float w0_3 = __ldg(&W[(col + 3) * 2]);
    float w1_3 = __ldg(&W[(col + 3) * 2 + 1]);
    float b_0  = __ldg(&b[col + 0]);
    float b_1  = __ldg(&b[col + 1]);
    float b_2  = __ldg(&b[col + 2]);
    float b_3  = __ldg(&b[col + 3]);

    long long row0 = (long long)blockIdx.x * (ROWS_PER_BLOCK * ITERS) + sub;

    const float2* __restrict__ xp = reinterpret_cast<const float2*>(x) + row0;
    float4* __restrict__       op = reinterpret_cast<float4*>(out) + row0 * TPR + lane;

    long long rows_left = (long long)n_rows - row0;

    #pragma unroll 8
    for (int i = 0; i < ITERS; i++) {
        if ((long long)i * ROWS_PER_BLOCK >= rows_left) break;

        float2 xx = __ldg(xp);         // broadcast across the 64 lanes of this row

        float4 y;
        y.x = fmaxf(fmaf(xx.x, w0_0, fmaf(xx.y, w1_0, b_0)), 0.0f);
        y.y = fmaxf(fmaf(xx.x, w0_1, fmaf(xx.y, w1_1, b_1)), 0.0f);
        y.z = fmaxf(fmaf(xx.x, w0_2, fmaf(xx.y, w1_2, b_2)), 0.0f);
        y.w = fmaxf(fmaf(xx.x, w0_3, fmaf(xx.y, w1_3, b_3)), 0.0f);

        __stcs(op, y);                 // streaming store: evict-first, never re-read

        xp += ROWS_PER_BLOCK;
        op += ROWS_PER_BLOCK * TPR;
    }
}

extern "C" void kernel_launch(void* const* d_in, const int* in_sizes, int n_in,
                              void* d_out, int out_size) {
    const float* x = (const float*)d_in[0];   // [B, N, 2]
    const float* W = (const float*)d_in[1];   // [256, 2]
    const float* b = (const float*)d_in[2];   // [256]
    float* out = (float*)d_out;               // [B, N, 256]

    int n_rows = in_sizes[0] / 2;             // B*N = 512000

    int rows_per_block = ROWS_PER_BLOCK * ITERS;   // 128
    int grid = (n_rows + rows_per_block - 1) / rows_per_block;   // 4000
    embeddings_kernel<<<grid, BLOCK_THREADS>>>(x, W, b, out, n_rows);
}

// round 5
// speedup vs baseline: 1.5628x; 1.0050x over previous
#include <cuda_runtime.h>

// relu(x @ W^T + b)
// x: [B*N, 2] f32, W: [256, 2] f32 row-major (W[d][i]), b: [256] f32
// out: [B*N, 256] f32.  n_rows = 512000.
//
// R5: warp-per-row (TPR=32). Each thread computes 8 columns as two chunks
// (lane*4 and lane*4+128) -> two fully-coalesced STG.128.CS per row.
// Halves redundant x broadcast loads, doubles per-thread store MLP,
// all-int32 addressing. No shared memory.

#define D_MODEL 256
#define TPR 32                         // one warp per row
#define BLOCK_THREADS 256
#define ROWS_PER_BLOCK 8               // 8 warps = 8 concurrent rows
#define ITERS 16                       // -> 128 rows per block

__global__ __launch_bounds__(BLOCK_THREADS)
void embeddings_kernel(const float* __restrict__ x,
                       const float* __restrict__ W,
                       const float* __restrict__ b,
                       float* __restrict__ out,
                       int n_rows) {
    int tid  = threadIdx.x;
    int lane = tid & 31;               // 0..31
    int sub  = tid >> 5;               // warp id in block -> row subgroup
    int colA = lane * 4;               // chunk A: cols [0,128)
    int colB = colA + 128;             // chunk B: cols [128,256)

    // Constants for this thread's 8 columns (one-time, L2 resident).
    float wA0x = __ldg(&W[(colA + 0) * 2]), wA0y = __ldg(&W[(colA + 0) * 2 + 1]);
    float wA1x = __ldg(&W[(colA + 1) * 2]), wA1y = __ldg(&W[(colA + 1) * 2 + 1]);
    float wA2x = __ldg(&W[(colA + 2) * 2]), wA2y = __ldg(&W[(colA + 2) * 2 + 1]);
    float wA3x = __ldg(&W[(colA + 3) * 2]), wA3y = __ldg(&W[(colA + 3) * 2 + 1]);
    float wB0x = __ldg(&W[(colB + 0) * 2]), wB0y = __ldg(&W[(colB + 0) * 2 + 1]);
    float wB1x = __ldg(&W[(colB + 1) * 2]), wB1y = __ldg(&W[(colB + 1) * 2 + 1]);
    float wB2x = __ldg(&W[(colB + 2) * 2]), wB2y = __ldg(&W[(colB + 2) * 2 + 1]);
    float wB3x = __ldg(&W[(colB + 3) * 2]), wB3y = __ldg(&W[(colB + 3) * 2 + 1]);
    float bA0 = __ldg(&b[colA + 0]), bA1 = __ldg(&b[colA + 1]);
    float bA2 = __ldg(&b[colA + 2]), bA3 = __ldg(&b[colA + 3]);
    float bB0 = __ldg(&b[colB + 0]), bB1 = __ldg(&b[colB + 1]);
    float bB2 = __ldg(&b[colB + 2]), bB3 = __ldg(&b[colB + 3]);

    int row0 = blockIdx.x * (ROWS_PER_BLOCK * ITERS) + sub;   // < 512000, fits int

    const float2* __restrict__ xp = reinterpret_cast<const float2*>(x) + row0;
    // float4 index: row*64 + lane; max 512000*64 = 32.7M, fits int
    float4* __restrict__ opA = reinterpret_cast<float4*>(out) + row0 * 64 + lane;
    float4* __restrict__ opB = opA + 32;                       // +128 floats

    int rows_left = n_rows - row0;

    #pragma unroll 4
    for (int i = 0; i < ITERS; i++) {
        if (i * ROWS_PER_BLOCK >= rows_left) break;

        float2 xx = __ldg(xp);         // one broadcast load per warp per row

        float4 ya, yb;
        ya.x = fmaxf(fmaf(xx.x, wA0x, fmaf(xx.y, wA0y, bA0)), 0.0f);
        ya.y = fmaxf(fmaf(xx.x, wA1x, fmaf(xx.y, wA1y, bA1)), 0.0f);
        ya.z = fmaxf(fmaf(xx.x, wA2x, fmaf(xx.y, wA2y, bA2)), 0.0f);
        ya.w = fmaxf(fmaf(xx.x, wA3x, fmaf(xx.y, wA3y, bA3)), 0.0f);
        yb.x = fmaxf(fmaf(xx.x, wB0x, fmaf(xx.y, wB0y, bB0)), 0.0f);
        yb.y = fmaxf(fmaf(xx.x, wB1x, fmaf(xx.y, wB1y, bB1)), 0.0f);
        yb.z = fmaxf(fmaf(xx.x, wB2x, fmaf(xx.y, wB2y, bB2)), 0.0f);
        yb.w = fmaxf(fmaf(xx.x, wB3x, fmaf(xx.y, wB3y, bB3)), 0.0f);

        __stcs(opA, ya);               // two independent coalesced streaming stores
        __stcs(opB, yb);

        xp  += ROWS_PER_BLOCK;
        opA += ROWS_PER_BLOCK * 64;
        opB += ROWS_PER_BLOCK * 64;
    }
}

extern "C" void kernel_launch(void* const* d_in, const int* in_sizes, int n_in,
                              void* d_out, int out_size) {
    const float* x = (const float*)d_in[0];   // [B, N, 2]
    const float* W = (const float*)d_in[1];   // [256, 2]
    const float* b = (const float*)d_in[2];   // [256]
    float* out = (float*)d_out;               // [B, N, 256]

    int n_rows = in_sizes[0] / 2;             // B*N = 512000

    int rows_per_block = ROWS_PER_BLOCK * ITERS;   // 128
    int grid = (n_rows + rows_per_block - 1) / rows_per_block;   // 4000
    embeddings_kernel<<<grid, BLOCK_THREADS>>>(x, W, b, out, n_rows);
}